// round 17
// baseline (speedup 1.0000x reference)
#include <cuda_runtime.h>

#define BB 8
#define CC 256
#define HH 96
#define WW 96
#define HW (HH*WW)          // 9216
#define PATCH 21
#define NP    (PATCH*PATCH) // 441
#define HALFP 10
#define DILP 2
#define TROW 136            // 96 + 2*20 halo

// Producers: 192 blocks, one dot unit each.
// unit = (b, cg, third): 32 channels x 3072 spatial floats.
// Reads 2 x 32 contiguous 12KB chunks; REDGs a 3072-float partial into g_D.
#define NPROD 192
#define TARGET 24           // dot units per batch (8 cg x 3 thirds)

// Consumers: 400 blocks, R16 y-span gather units (write-locality layout).
#define NCONS 400
#define GRID  (NPROD + NCONS)   // 592 = 148*4
#define NUNIT   420
#define NCOARSE 252         // batches 0..5: (b,py,yhalf) span 48
#define NDBL    20          // blocks 0..19 take second unit 400+cid

__device__ float g_D[BB * HW];     // zero-init at load; re-zeroed each replay
__device__ int   g_cnt[BB];        // completed dot units per batch
__device__ int   g_done;           // consumer phase-1 arrivals
__device__ int   g_done2;          // consumer phase-2 arrivals (reset gate)

// ---------------- consumer: one y-span gather unit (R16, proven) -----------
template <int SPAN>
__device__ __forceinline__ void do_gather(float* tile, int b, int py, int y0,
                                          int tid, float* __restrict__ out) {
    for (int i = tid; i < SPAN * TROW; i += 256) tile[i] = 0.f;

    if (tid == 0) {
        volatile int* c = &g_cnt[b];
        while (*c < TARGET) __nanosleep(100);
        __threadfence();                   // acquire
    }
    __syncthreads();

    const float4* __restrict__ D4 = (const float4*)g_D;
    const int syBase = y0 + (py - HALFP) * DILP;
    for (int i = tid; i < SPAN * 24; i += 256) {
        const int rr = i / 24;
        const int x4 = i - rr * 24;
        const int sy = syBase + rr;
        if ((unsigned)sy < (unsigned)HH) {
            float4 v = D4[(b * HH + sy) * 24 + x4];
            *(float4*)(tile + rr * TROW + 20 + x4 * 4) = v;
        }
    }
    __syncthreads();

    float4* __restrict__ O4 = (float4*)out;
    const size_t pbase = (size_t)b * NP + py * PATCH;
    for (int i = tid; i < PATCH * SPAN * 24; i += 256) {
        const int x4 = i % 24;
        const int t  = i / 24;
        const int yr = t % SPAN;
        const int px = t / SPAN;

        const float2* sp =
            (const float2*)(tile + yr * TROW + px * 2 + x4 * 4);
        float2 lo = sp[0];
        float2 hi = sp[1];

        O4[(pbase + px) * (HW / 4) + (size_t)(y0 + yr) * 24 + x4] =
            make_float4(lo.x, lo.y, hi.x, hi.y);
    }
    __syncthreads();
}

__device__ __forceinline__ void run_unit(int u, float* tile, int tid,
                                         float* __restrict__ out) {
    if (u < NCOARSE) {                     // batches 0..5, span 48
        const int b = u / 42;
        const int r = u - b * 42;
        do_gather<48>(tile, b, r >> 1, (r & 1) * 48, tid, out);
    } else {                               // batches 6..7, span 24
        const int v = u - NCOARSE;
        const int b = 6 + v / 84;
        const int r = v % 84;
        do_gather<24>(tile, b, r >> 2, (r & 3) * 24, tid, out);
    }
}

__global__ void __launch_bounds__(256, 4) fused_kernel(
        const float* __restrict__ a,
        const float* __restrict__ b,
        float* __restrict__ out) {
    __shared__ float tile[48 * TROW];      // 26112 B (consumer only)

    const int tid = threadIdx.x;
    const int bid = blockIdx.x;

    if (bid < NPROD) {
        // ========== PRODUCER: one contiguous-chunk dot unit ================
        const int b_    = bid / TARGET;            // batch
        const int r     = bid - b_ * TARGET;
        const int cg    = r / 3;                   // 32-channel group
        const int third = r - cg * 3;              // spatial third

        const float4* __restrict__ A4 =
            (const float4*)a + (size_t)b_ * CC * 2304 + third * 768;
        const float4* __restrict__ B4 =
            (const float4*)b + (size_t)b_ * CC * 2304 + third * 768;
        const int c0 = cg * 32;

        float4 s0 = make_float4(0.f,0.f,0.f,0.f);
        float4 s1 = make_float4(0.f,0.f,0.f,0.f);
        float4 s2 = make_float4(0.f,0.f,0.f,0.f);

        #pragma unroll 2
        for (int c = 0; c < 32; ++c) {
            const size_t off = (size_t)(c0 + c) * 2304;  // float4 units
            float4 x0 = A4[off + tid];
            float4 x1 = A4[off + tid + 256];
            float4 x2 = A4[off + tid + 512];
            float4 y0 = B4[off + tid];
            float4 y1 = B4[off + tid + 256];
            float4 y2 = B4[off + tid + 512];
            s0.x = fmaf(x0.x, y0.x, s0.x);  s0.y = fmaf(x0.y, y0.y, s0.y);
            s0.z = fmaf(x0.z, y0.z, s0.z);  s0.w = fmaf(x0.w, y0.w, s0.w);
            s1.x = fmaf(x1.x, y1.x, s1.x);  s1.y = fmaf(x1.y, y1.y, s1.y);
            s1.z = fmaf(x1.z, y1.z, s1.z);  s1.w = fmaf(x1.w, y1.w, s1.w);
            s2.x = fmaf(x2.x, y2.x, s2.x);  s2.y = fmaf(x2.y, y2.y, s2.y);
            s2.z = fmaf(x2.z, y2.z, s2.z);  s2.w = fmaf(x2.w, y2.w, s2.w);
        }

        // accumulate partial into g_D (zeroed by previous replay's epilogue)
        float* d = g_D + b_ * HW + third * 3072;
        atomicAdd(d + 4*tid + 0,    s0.x); atomicAdd(d + 4*tid + 1,    s0.y);
        atomicAdd(d + 4*tid + 2,    s0.z); atomicAdd(d + 4*tid + 3,    s0.w);
        atomicAdd(d + 4*(tid+256)+0,s1.x); atomicAdd(d + 4*(tid+256)+1,s1.y);
        atomicAdd(d + 4*(tid+256)+2,s1.z); atomicAdd(d + 4*(tid+256)+3,s1.w);
        atomicAdd(d + 4*(tid+512)+0,s2.x); atomicAdd(d + 4*(tid+512)+1,s2.y);
        atomicAdd(d + 4*(tid+512)+2,s2.z); atomicAdd(d + 4*(tid+512)+3,s2.w);

        __threadfence();                   // all threads: publish partials
        __syncthreads();
        if (tid == 0) atomicAdd(&g_cnt[b_], 1);
    } else {
        // ===== CONSUMER: y-span gather (R16) + epilogue zero of g_D ========
        const int cid = bid - NPROD;

        run_unit(cid, tile, tid, out);
        if (cid < NDBL)
            run_unit(NCONS + cid, tile, tid, out);

        // phase 1: all consumers done reading g_D
        if (tid == 0) {
            __threadfence();
            atomicAdd(&g_done, 1);
            volatile int* dd = &g_done;
            while (*dd < NCONS) __nanosleep(100);
        }
        __syncthreads();

        // zero g_D for the next replay (blocks 0..71 cover it exactly:
        // 72 blocks x 256 threads = 18432 float4 = BB*HW/4)
        {
            const int i = cid * 256 + tid;
            if (i < BB * HW / 4)
                ((float4*)g_D)[i] = make_float4(0.f,0.f,0.f,0.f);
        }
        __syncthreads();

        // phase 2: last consumer resets all sync state
        if (tid == 0) {
            __threadfence();
            int d2 = atomicAdd(&g_done2, 1);
            if (d2 == NCONS - 1) {
                #pragma unroll
                for (int i = 0; i < BB; ++i) g_cnt[i] = 0;
                g_done  = 0;
                g_done2 = 0;
                __threadfence();
            }
        }
    }
}

extern "C" void kernel_launch(void* const* d_in, const int* in_sizes, int n_in,
                              void* d_out, int out_size) {
    const float* in1 = (const float*)d_in[0];
    const float* in2 = (const float*)d_in[1];
    float* out = (float*)d_out;

    fused_kernel<<<GRID, 256>>>(in1, in2, out);
}